// round 7
// baseline (speedup 1.0000x reference)
#include <cuda_runtime.h>

#define Nn   1024
#define Cc   64
#define HID  128
#define TS   16
#define NTS  (Nn / TS)                  // 64
#define NUNITS (NTS * (NTS + 1) / 2)    // 2080
#define NPROD 256                       // producer blocks (4 n-cols each)

// interleaved: g_p[h*Nn + n] = (pi[h,n], pj[h,n])
__device__ float2 g_p[HID * Nn];
__device__ unsigned g_ready;   // producers done counter (reset each run)
__device__ unsigned g_done;    // exit counter (reset each run)

__device__ __forceinline__ float tanh_apx(float x) {
    float y;
    asm("tanh.approx.f32 %0, %1;" : "=f"(y) : "f"(x));
    return y;
}

__global__ __launch_bounds__(256, 6)
void fused_kernel(const float* __restrict__ x,
                  const float* __restrict__ W1,
                  const float* __restrict__ b1,
                  const float* __restrict__ W2,
                  const float* __restrict__ b2,
                  float* __restrict__ out) {
    __shared__ __align__(16) float2 pS[HID][2 * TS];
    __shared__ float w2s[HID];

    const int tid = threadIdx.x;
    const int bid = blockIdx.x;

    // ------------------------------------------------------------------
    // Phase 1: producer blocks compute prep slice (4 n-columns)
    //   pi[h,n] = sum_c W1[h,Cc+c]*tanh(x[c,n]) + b1[h]
    //   pj[h,n] = sum_c W1[h,  c]*tanh(x[c,n])
    // ------------------------------------------------------------------
    if (bid < NPROD) {
        __shared__ float t_s[Cc][4];
        const int n0 = bid * 4;
        if (tid < Cc * 4) {
            int c = tid >> 2, n = tid & 3;
            t_s[c][n] = tanhf(x[c * Nn + n0 + n]);   // precise tanh here
        }
        __syncthreads();

        const int h  = tid & 127;
        const int ng = (tid >> 7) * 2;     // 0 or 2
        const float bb = b1[h];
        float accj0 = 0.f, accj1 = 0.f, acci0 = bb, acci1 = bb;

#pragma unroll
        for (int c = 0; c < Cc; c++) {
            float wj = W1[h * (2 * Cc) + c];
            float wi = W1[h * (2 * Cc) + Cc + c];
            float t0 = t_s[c][ng + 0];
            float t1 = t_s[c][ng + 1];
            accj0 = fmaf(wj, t0, accj0);
            acci0 = fmaf(wi, t0, acci0);
            accj1 = fmaf(wj, t1, accj1);
            acci1 = fmaf(wi, t1, acci1);
        }
        g_p[h * Nn + n0 + ng + 0] = make_float2(acci0, accj0);
        g_p[h * Nn + n0 + ng + 1] = make_float2(acci1, accj1);

        __syncthreads();
        if (tid == 0) {
            unsigned* rp = &g_ready;
            asm volatile("red.release.gpu.global.add.u32 [%0], 1;" :: "l"(rp) : "memory");
        }
    }

    // ------------------------------------------------------------------
    // Gate: wait until all producers have published g_p
    // ------------------------------------------------------------------
    if (tid == 0) {
        unsigned* rp = &g_ready;
        unsigned r;
        do {
            asm volatile("ld.acquire.gpu.global.u32 %0, [%1];" : "=r"(r) : "l"(rp) : "memory");
            if (r >= NPROD) break;
            __nanosleep(64);
        } while (true);
    }
    __syncthreads();

    // ------------------------------------------------------------------
    // Phase 2: pair body (R3 winner, unchanged)
    // ------------------------------------------------------------------
    int rem = bid, a = 0, len = NTS;
    while (rem >= len) { rem -= len; a++; len--; }
    const int b  = a + rem;
    const int i0 = a * TS, j0 = b * TS;

    if (tid < HID) w2s[tid] = W2[tid];

    for (int t = tid; t < HID * 16; t += 256) {
        int h    = t >> 4;
        int q    = t & 15;
        int side = q >> 3;
        int c    = (q & 7) * 2;
        int src  = side ? j0 : i0;
        float4 v = *(const float4*)&g_p[h * Nn + src + c];
        *(float4*)&pS[h][side * TS + c] = v;
    }
    __syncthreads();

    const int ii = tid >> 4;
    const int jj = tid & 15;

    float acc1 = 0.0f, acc2 = 0.0f;
#pragma unroll 8
    for (int h = 0; h < HID; h++) {
        float2 ai = pS[h][ii];
        float2 aj = pS[h][TS + jj];
        float  w  = w2s[h];
        acc1 = fmaf(w, tanh_apx(ai.x + aj.y), acc1);   // e[i,j]
        acc2 = fmaf(w, tanh_apx(aj.x + ai.y), acc2);   // e[j,i]
    }

    const float v  = acc1 + acc2 + 2.0f * b2[0];
    const int gi = i0 + ii, gj = j0 + jj;
    out[gi * Nn + gj] = v;
    out[gj * Nn + gi] = v;

    // ------------------------------------------------------------------
    // Exit: last block resets counters for the next (graph-replayed) run
    // ------------------------------------------------------------------
    __syncthreads();
    if (tid == 0) {
        unsigned d = atomicAdd(&g_done, 1);
        if (d == NUNITS - 1) {       // last block to finish
            g_ready = 0;
            __threadfence();
            g_done = 0;
        }
    }
}

extern "C" void kernel_launch(void* const* d_in, const int* in_sizes, int n_in,
                              void* d_out, int out_size) {
    const float* x  = (const float*)d_in[0];
    const float* W1 = (const float*)d_in[1];
    const float* b1 = (const float*)d_in[2];
    const float* W2 = (const float*)d_in[3];
    const float* b2 = (const float*)d_in[4];
    float* out = (float*)d_out;

    fused_kernel<<<NUNITS, 256>>>(x, W1, b1, W2, b2, out);
}

// round 8
// speedup vs baseline: 1.4397x; 1.4397x over previous
#include <cuda_runtime.h>

#define Nn   1024
#define Cc   64
#define HID  128
#define TS   16                         // output sub-tile edge
#define NTS  (Nn / TS)                  // 64
#define NUNITS (NTS * (NTS + 1) / 2)    // 2080

// interleaved: g_p[h*Nn + n] = (pi[h,n], pj[h,n])
__device__ float2 g_p[HID * Nn];

__device__ __forceinline__ float tanh_apx(float x) {
    float y;
    asm("tanh.approx.f32 %0, %1;" : "=f"(y) : "f"(x));
    return y;
}

// ---------------------------------------------------------------------------
// prep: pi[h,n] = sum_c W1[h,Cc+c]*tanh(x[c,n]) + b1[h]
//       pj[h,n] = sum_c W1[h,   c]*tanh(x[c,n])
// grid 256 blocks x 256 threads; block = 4-col n chunk;
// thread = (h = tid&127, 2 cols by tid>>7). Short critical path (~128 FMA).
// Signals PDL completion after its g_p stores.
// ---------------------------------------------------------------------------
#define NCH 4
__global__ __launch_bounds__(256) void prep_kernel(const float* __restrict__ x,
                                                   const float* __restrict__ W1,
                                                   const float* __restrict__ b1) {
    __shared__ float t_s[Cc][NCH];
    const int n0  = blockIdx.x * NCH;
    const int tid = threadIdx.x;

    if (tid < Cc * NCH) {
        int c = tid / NCH, n = tid % NCH;
        t_s[c][n] = tanhf(x[c * Nn + n0 + n]);   // precise tanh in pre-pass
    }
    __syncthreads();

    const int h  = tid & 127;
    const int ng = (tid >> 7) * 2;     // 0 or 2
    const float bb = b1[h];
    float accj0 = 0.f, accj1 = 0.f, acci0 = bb, acci1 = bb;

#pragma unroll
    for (int c = 0; c < Cc; c++) {
        float wj = W1[h * (2 * Cc) + c];
        float wi = W1[h * (2 * Cc) + Cc + c];
        float t0 = t_s[c][ng + 0];
        float t1 = t_s[c][ng + 1];
        accj0 = fmaf(wj, t0, accj0);
        acci0 = fmaf(wi, t0, acci0);
        accj1 = fmaf(wj, t1, accj1);
        acci1 = fmaf(wi, t1, acci1);
    }
    g_p[h * Nn + n0 + ng + 0] = make_float2(acci0, accj0);
    g_p[h * Nn + n0 + ng + 1] = make_float2(acci1, accj1);

    // all stores in this block done -> allow dependents
    __threadfence();
    __syncthreads();
    asm volatile("griddepcontrol.launch_dependents;" ::: "memory");
}

// ---------------------------------------------------------------------------
// pair (R3 winner): triangular unit (a <= b), 256 threads, one (i,j)/thread:
//   v = sum_h w2[h]*(tanh(pi_i + pj_j) + tanh(pi_j + pj_i)) + 2*b2
// PDL: setup overlaps prep; griddepcontrol.wait before reading g_p.
// ---------------------------------------------------------------------------
__global__ __launch_bounds__(256) void pair_kernel(const float* __restrict__ W2,
                                                   const float* __restrict__ b2,
                                                   float* __restrict__ out) {
    __shared__ __align__(16) float2 pS[HID][2 * TS];   // [h][0..15]=i, [16..31]=j
    __shared__ float w2s[HID];

    // triangular decode (independent of prep)
    int rem = blockIdx.x, a = 0, len = NTS;
    while (rem >= len) { rem -= len; a++; len--; }
    const int b  = a + rem;
    const int i0 = a * TS, j0 = b * TS;

    const int tid = threadIdx.x;
    if (tid < HID) w2s[tid] = W2[tid];
    const float bb2 = 2.0f * b2[0];

    // wait for prep grid's writes to be visible
    asm volatile("griddepcontrol.wait;" ::: "memory");

    // stage: 128 h x (16 i-cols + 16 j-cols) float2, as float4 (2 float2 each)
    for (int t = tid; t < HID * 16; t += 256) {
        int h    = t >> 4;
        int q    = t & 15;
        int side = q >> 3;            // 0 = i-side, 1 = j-side
        int c    = (q & 7) * 2;       // float2 column offset
        int src  = side ? j0 : i0;
        float4 v = *(const float4*)&g_p[h * Nn + src + c];
        *(float4*)&pS[h][side * TS + c] = v;
    }
    __syncthreads();

    const int ii = tid >> 4;      // 0..15
    const int jj = tid & 15;      // 0..15

    float acc1 = 0.0f, acc2 = 0.0f;
#pragma unroll 8
    for (int h = 0; h < HID; h++) {
        float2 ai = pS[h][ii];          // (pi_i, pj_i)
        float2 aj = pS[h][TS + jj];     // (pi_j, pj_j)
        float  w  = w2s[h];
        acc1 = fmaf(w, tanh_apx(ai.x + aj.y), acc1);   // e[i,j]
        acc2 = fmaf(w, tanh_apx(aj.x + ai.y), acc2);   // e[j,i]
    }

    const float v  = acc1 + acc2 + bb2;
    const int gi = i0 + ii, gj = j0 + jj;
    out[gi * Nn + gj] = v;
    out[gj * Nn + gi] = v;     // mirror (same value by construction)
}

extern "C" void kernel_launch(void* const* d_in, const int* in_sizes, int n_in,
                              void* d_out, int out_size) {
    const float* x  = (const float*)d_in[0];
    const float* W1 = (const float*)d_in[1];
    const float* b1 = (const float*)d_in[2];
    const float* W2 = (const float*)d_in[3];
    const float* b2 = (const float*)d_in[4];
    float* out = (float*)d_out;

    prep_kernel<<<Nn / NCH, 256>>>(x, W1, b1);

    // pair with programmatic dependent launch: overlaps its prologue with prep
    cudaLaunchConfig_t cfg = {};
    cfg.gridDim  = dim3(NUNITS);
    cfg.blockDim = dim3(256);
    cfg.dynamicSmemBytes = 0;
    cfg.stream = 0;
    cudaLaunchAttribute attr[1];
    attr[0].id = cudaLaunchAttributeProgrammaticStreamSerialization;
    attr[0].val.programmaticStreamSerializationAllowed = 1;
    cfg.attrs = attr;
    cfg.numAttrs = 1;
    cudaLaunchKernelEx(&cfg, pair_kernel, W2, b2, (float*)out);
}

// round 9
// speedup vs baseline: 2.1470x; 1.4913x over previous
#include <cuda_runtime.h>

#define Nn   1024
#define Cc   64
#define HID  128
#define TS   16                         // output sub-tile edge
#define NTS  (Nn / TS)                  // 64
#define NUNITS (NTS * (NTS + 1) / 2)    // 2080
#define PNCH 32                         // n-cols per prep block

// interleaved: g_p[h*Nn + n] = (pi[h,n], pj[h,n])
__device__ float2 g_p[HID * Nn];

__device__ __forceinline__ float tanh_apx(float x) {
    float y;
    asm("tanh.approx.f32 %0, %1;" : "=f"(y) : "f"(x));
    return y;
}

// ---------------------------------------------------------------------------
// prep: pi[h,n] = sum_c W1[h,Cc+c]*tanh(x[c,n]) + b1[h]
//       pj[h,n] = sum_c W1[h,   c]*tanh(x[c,n])
// grid (32,4) x 256 threads. Block = 32 n-cols x 32 h-rows.
// Warp-uniform h -> W1 loads are broadcasts; lane = n -> coalesced x/g_p.
// ---------------------------------------------------------------------------
__global__ __launch_bounds__(256) void prep_kernel(const float* __restrict__ x,
                                                   const float* __restrict__ W1,
                                                   const float* __restrict__ b1) {
    __shared__ float t_s[Cc][PNCH];          // 8 KB
    const int n0   = blockIdx.x * PNCH;
    const int tid  = threadIdx.x;
    const int lane = tid & 31;
    const int w    = tid >> 5;               // warp 0..7

    // stage tanh(x) for this n-range: 64*32 = 2048 values, 8 per thread
    for (int k = tid; k < Cc * PNCH; k += 256) {
        int c = k >> 5, n = k & 31;
        t_s[c][n] = tanhf(x[c * Nn + n0 + n]);   // coalesced 32-wide rows
    }
    __syncthreads();

    // warp w handles h = by*32 + w*4 + g, g=0..3 ; lane = n
#pragma unroll
    for (int g = 0; g < 4; g++) {
        const int h = blockIdx.y * 32 + w * 4 + g;
        const float bb = b1[h];              // uniform
        float acci = bb, accj = 0.0f;
#pragma unroll
        for (int c = 0; c < Cc; c++) {
            float wj = W1[h * (2 * Cc) + c];        // warp-uniform broadcast
            float wi = W1[h * (2 * Cc) + Cc + c];   // warp-uniform broadcast
            float t  = t_s[c][lane];
            accj = fmaf(wj, t, accj);
            acci = fmaf(wi, t, acci);
        }
        g_p[h * Nn + n0 + lane] = make_float2(acci, accj);   // coalesced 8B
    }

    // PDL: this block's g_p stores done -> allow dependents
    __threadfence();
    __syncthreads();
    asm volatile("griddepcontrol.launch_dependents;" ::: "memory");
}

// ---------------------------------------------------------------------------
// pair (R3 winner, untouched): triangular unit (a <= b), 256 threads,
// one (i,j) per thread:
//   v = sum_h w2[h]*(tanh(pi_i + pj_j) + tanh(pi_j + pj_i)) + 2*b2
// writes out[i,j] and out[j,i].
// ---------------------------------------------------------------------------
__global__ __launch_bounds__(256) void pair_kernel(const float* __restrict__ W2,
                                                   const float* __restrict__ b2,
                                                   float* __restrict__ out) {
    __shared__ __align__(16) float2 pS[HID][2 * TS];   // [h][0..15]=i, [16..31]=j
    __shared__ float w2s[HID];

    // triangular decode (independent of prep)
    int rem = blockIdx.x, a = 0, len = NTS;
    while (rem >= len) { rem -= len; a++; len--; }
    const int b  = a + rem;
    const int i0 = a * TS, j0 = b * TS;

    const int tid = threadIdx.x;
    if (tid < HID) w2s[tid] = W2[tid];
    const float bb2 = 2.0f * b2[0];

    // wait for prep grid's writes to be visible
    asm volatile("griddepcontrol.wait;" ::: "memory");

    // stage: 128 h x (16 i-cols + 16 j-cols) float2, as float4 (2 float2 each)
    for (int t = tid; t < HID * 16; t += 256) {
        int h    = t >> 4;
        int q    = t & 15;
        int side = q >> 3;            // 0 = i-side, 1 = j-side
        int c    = (q & 7) * 2;       // float2 column offset
        int src  = side ? j0 : i0;
        float4 v = *(const float4*)&g_p[h * Nn + src + c];
        *(float4*)&pS[h][side * TS + c] = v;
    }
    __syncthreads();

    const int ii = tid >> 4;      // 0..15
    const int jj = tid & 15;      // 0..15

    float acc1 = 0.0f, acc2 = 0.0f;
#pragma unroll 8
    for (int h = 0; h < HID; h++) {
        float2 ai = pS[h][ii];          // (pi_i, pj_i)
        float2 aj = pS[h][TS + jj];     // (pi_j, pj_j)
        float  w  = w2s[h];
        acc1 = fmaf(w, tanh_apx(ai.x + aj.y), acc1);   // e[i,j]
        acc2 = fmaf(w, tanh_apx(aj.x + ai.y), acc2);   // e[j,i]
    }

    const float v  = acc1 + acc2 + bb2;
    const int gi = i0 + ii, gj = j0 + jj;
    out[gi * Nn + gj] = v;
    out[gj * Nn + gi] = v;     // mirror (same value by construction)
}

extern "C" void kernel_launch(void* const* d_in, const int* in_sizes, int n_in,
                              void* d_out, int out_size) {
    const float* x  = (const float*)d_in[0];
    const float* W1 = (const float*)d_in[1];
    const float* b1 = (const float*)d_in[2];
    const float* W2 = (const float*)d_in[3];
    const float* b2 = (const float*)d_in[4];
    float* out = (float*)d_out;

    prep_kernel<<<dim3(32, 4), 256>>>(x, W1, b1);

    // pair with programmatic dependent launch: overlaps its prologue with prep
    cudaLaunchConfig_t cfg = {};
    cfg.gridDim  = dim3(NUNITS);
    cfg.blockDim = dim3(256);
    cfg.dynamicSmemBytes = 0;
    cfg.stream = 0;
    cudaLaunchAttribute attr[1];
    attr[0].id = cudaLaunchAttributeProgrammaticStreamSerialization;
    attr[0].val.programmaticStreamSerializationAllowed = 1;
    cfg.attrs = attr;
    cfg.numAttrs = 1;
    cudaLaunchKernelEx(&cfg, pair_kernel, W2, b2, (float*)out);
}

// round 10
// speedup vs baseline: 2.2394x; 1.0430x over previous
#include <cuda_runtime.h>

#define Nn   1024
#define Cc   64
#define HID  128
#define TS   16                         // output sub-tile edge
#define NTS  (Nn / TS)                  // 64
#define NUNITS (NTS * (NTS + 1) / 2)    // 2080
#define PNCH 32                         // n-cols per prep block

// interleaved: g_p[h*Nn + n] = (pi[h,n], pj[h,n])
__device__ float2 g_p[HID * Nn];

__device__ __forceinline__ float tanh_apx(float x) {
    float y;
    asm("tanh.approx.f32 %0, %1;" : "=f"(y) : "f"(x));
    return y;
}

// ---------------------------------------------------------------------------
// prep (R9 winner, unchanged): warp-uniform h, coalesced n.
// ---------------------------------------------------------------------------
__global__ __launch_bounds__(256) void prep_kernel(const float* __restrict__ x,
                                                   const float* __restrict__ W1,
                                                   const float* __restrict__ b1) {
    __shared__ float t_s[Cc][PNCH];
    const int n0   = blockIdx.x * PNCH;
    const int tid  = threadIdx.x;
    const int lane = tid & 31;
    const int w    = tid >> 5;

    for (int k = tid; k < Cc * PNCH; k += 256) {
        int c = k >> 5, n = k & 31;
        t_s[c][n] = tanhf(x[c * Nn + n0 + n]);
    }
    __syncthreads();

#pragma unroll
    for (int g = 0; g < 4; g++) {
        const int h = blockIdx.y * 32 + w * 4 + g;
        const float bb = b1[h];
        float acci = bb, accj = 0.0f;
#pragma unroll
        for (int c = 0; c < Cc; c++) {
            float wj = W1[h * (2 * Cc) + c];
            float wi = W1[h * (2 * Cc) + Cc + c];
            float t  = t_s[c][lane];
            accj = fmaf(wj, t, accj);
            acci = fmaf(wi, t, acci);
        }
        g_p[h * Nn + n0 + lane] = make_float2(acci, accj);
    }

    __threadfence();
    __syncthreads();
    asm volatile("griddepcontrol.launch_dependents;" ::: "memory");
}

// ---------------------------------------------------------------------------
// pair: 16x16 triangular unit, 256 threads = 2 h-groups x 128.
// Thread (g, ii, jj2): accumulates over h in [64g, 64g+64) for (i=ii, j=2jj2,2jj2+1):
//   acc_B = sum_h w2[h]*( tanh(pi_i+pj_jB) + tanh(pi_jB+pj_i) )
// Groups combined via smem; out[i,j]=out[j,i]=acc+2*b2.
// ---------------------------------------------------------------------------
__global__ __launch_bounds__(256) void pair_kernel(const float* __restrict__ W2,
                                                   const float* __restrict__ b2,
                                                   float* __restrict__ out) {
    __shared__ __align__(16) float2 pS[HID][2 * TS];   // [h][0..15]=i, [16..31]=j
    __shared__ float w2s[HID];
    __shared__ float red[TS * TS];                     // group-0 partials

    // triangular decode (independent of prep)
    int rem = blockIdx.x, a = 0, len = NTS;
    while (rem >= len) { rem -= len; a++; len--; }
    const int b  = a + rem;
    const int i0 = a * TS, j0 = b * TS;

    const int tid = threadIdx.x;
    if (tid < HID) w2s[tid] = W2[tid];
    const float bb2 = 2.0f * b2[0];

    asm volatile("griddepcontrol.wait;" ::: "memory");

    // stage: 128 h x (16 i + 16 j) float2, as float4
    for (int t = tid; t < HID * 16; t += 256) {
        int h    = t >> 4;
        int q    = t & 15;
        int side = q >> 3;
        int c    = (q & 7) * 2;
        int src  = side ? j0 : i0;
        float4 v = *(const float4*)&g_p[h * Nn + src + c];
        *(float4*)&pS[h][side * TS + c] = v;
    }
    __syncthreads();

    const int g   = tid >> 7;        // h-group 0/1
    const int t2  = tid & 127;
    const int ii  = t2 >> 3;         // 0..15
    const int jj2 = t2 & 7;          // 0..7  -> j = 2*jj2, 2*jj2+1
    const int h0  = g * 64;

    float acc0 = 0.0f, acc1 = 0.0f;
#pragma unroll 8
    for (int hl = 0; hl < 64; hl++) {
        const int h = h0 + hl;
        float2 ai = pS[h][ii];                             // (pi_i, pj_i)
        float4 aj = *(const float4*)&pS[h][TS + 2 * jj2];  // (pi_j0,pj_j0,pi_j1,pj_j1)
        float  w  = w2s[h];
        acc0 = fmaf(w, tanh_apx(ai.x + aj.y) + tanh_apx(aj.x + ai.y), acc0);
        acc1 = fmaf(w, tanh_apx(ai.x + aj.w) + tanh_apx(aj.z + ai.y), acc1);
    }

    // combine the two h-groups
    if (g == 0) {
        red[ii * TS + jj2 * 2 + 0] = acc0;
        red[ii * TS + jj2 * 2 + 1] = acc1;
    }
    __syncthreads();
    if (g == 1) {
        const float v0 = red[ii * TS + jj2 * 2 + 0] + acc0 + bb2;
        const float v1 = red[ii * TS + jj2 * 2 + 1] + acc1 + bb2;
        const int gi = i0 + ii;
        const int gj = j0 + jj2 * 2;
        *(float2*)&out[gi * Nn + gj] = make_float2(v0, v1);  // upper, coalesced
        out[(gj + 0) * Nn + gi] = v0;                        // mirror
        out[(gj + 1) * Nn + gi] = v1;
    }
}

extern "C" void kernel_launch(void* const* d_in, const int* in_sizes, int n_in,
                              void* d_out, int out_size) {
    const float* x  = (const float*)d_in[0];
    const float* W1 = (const float*)d_in[1];
    const float* b1 = (const float*)d_in[2];
    const float* W2 = (const float*)d_in[3];
    const float* b2 = (const float*)d_in[4];
    float* out = (float*)d_out;

    prep_kernel<<<dim3(32, 4), 256>>>(x, W1, b1);

    cudaLaunchConfig_t cfg = {};
    cfg.gridDim  = dim3(NUNITS);
    cfg.blockDim = dim3(256);
    cfg.dynamicSmemBytes = 0;
    cfg.stream = 0;
    cudaLaunchAttribute attr[1];
    attr[0].id = cudaLaunchAttributeProgrammaticStreamSerialization;
    attr[0].val.programmaticStreamSerializationAllowed = 1;
    cfg.attrs = attr;
    cfg.numAttrs = 1;
    cudaLaunchKernelEx(&cfg, pair_kernel, W2, b2, (float*)out);
}

// round 11
// speedup vs baseline: 2.3385x; 1.0442x over previous
#include <cuda_runtime.h>
#include <cuda_fp16.h>

#define Nn   1024
#define Cc   64
#define HID  128
#define TS   16                         // output sub-tile edge
#define NTS  (Nn / TS)                  // 64
#define NUNITS (NTS * (NTS + 1) / 2)    // 2080
#define PNCH 32                         // n-cols per prep block

// packed half2 operand arrays (written by prep)
__device__ __half2 g_pid[HID * Nn];        // (pi_n, pi_n)
__device__ __half2 g_pjd[HID * Nn];        // (pj_n, pj_n)
__device__ __half2 g_pip[HID * Nn / 2];    // (pi_n, pi_{n+1}), n even
__device__ __half2 g_pjp[HID * Nn / 2];    // (pj_n, pj_{n+1}), n even

__device__ __forceinline__ __half2 tanh2(__half2 x) {
    unsigned xi = *(unsigned*)&x, yi;
    asm("tanh.approx.f16x2 %0, %1;" : "=r"(yi) : "r"(xi));
    return *(__half2*)&yi;
}

// ---------------------------------------------------------------------------
// prep: fp32 compute (precise tanhf), emits pre-packed half2 operands.
// grid (32,4) x 256; warp-uniform h, lane = n (coalesced).
// ---------------------------------------------------------------------------
__global__ __launch_bounds__(256) void prep_kernel(const float* __restrict__ x,
                                                   const float* __restrict__ W1,
                                                   const float* __restrict__ b1) {
    __shared__ float t_s[Cc][PNCH];
    const int n0   = blockIdx.x * PNCH;
    const int tid  = threadIdx.x;
    const int lane = tid & 31;
    const int w    = tid >> 5;

    for (int k = tid; k < Cc * PNCH; k += 256) {
        int c = k >> 5, n = k & 31;
        t_s[c][n] = tanhf(x[c * Nn + n0 + n]);
    }
    __syncthreads();

#pragma unroll
    for (int g = 0; g < 4; g++) {
        const int h = blockIdx.y * 32 + w * 4 + g;
        const float bb = b1[h];
        float acci = bb, accj = 0.0f;
#pragma unroll
        for (int c = 0; c < Cc; c++) {
            float wj = W1[h * (2 * Cc) + c];        // warp-uniform broadcast
            float wi = W1[h * (2 * Cc) + Cc + c];
            float t  = t_s[c][lane];
            accj = fmaf(wj, t, accj);
            acci = fmaf(wi, t, acci);
        }
        const int n = n0 + lane;
        float acciN = __shfl_down_sync(0xffffffffu, acci, 1);
        float accjN = __shfl_down_sync(0xffffffffu, accj, 1);
        g_pid[h * Nn + n] = __floats2half2_rn(acci, acci);
        g_pjd[h * Nn + n] = __floats2half2_rn(accj, accj);
        if ((lane & 1) == 0) {
            g_pip[h * (Nn >> 1) + (n >> 1)] = __floats2half2_rn(acci, acciN);
            g_pjp[h * (Nn >> 1) + (n >> 1)] = __floats2half2_rn(accj, accjN);
        }
    }

    __threadfence();
    __syncthreads();
    asm volatile("griddepcontrol.launch_dependents;" ::: "memory");
}

// ---------------------------------------------------------------------------
// pair: 16x16 triangular unit, 256 threads = 2 h-groups x 128.
// Thread (g, ii, jj2): 1 i x 2 j over 64 h. Per h: 2 packed tanh evaluate
// both directions for both j:
//   e  = tanh2(dup(pi_i) + (pj_j0,pj_j1))
//   t  = tanh2((pi_j0,pi_j1) + dup(pj_i))
//   acc{0,1} += w2[h] * (e+t).{lo,hi}   (fp32 accumulate)
// ---------------------------------------------------------------------------
__global__ __launch_bounds__(256) void pair_kernel(const float* __restrict__ W2,
                                                   const float* __restrict__ b2,
                                                   float* __restrict__ out) {
    __shared__ __align__(16) __half2 aeS[HID][TS];       // dup(pi_i)   8KB
    __shared__ __align__(16) __half2 atS[HID][TS];       // dup(pj_i)   8KB
    __shared__ __align__(16) __half2 bjP[HID][TS / 2];   // pj j-pairs  4KB
    __shared__ __align__(16) __half2 biP[HID][TS / 2];   // pi j-pairs  4KB
    __shared__ float w2s[HID];
    __shared__ float red[TS * TS];

    // triangular decode
    int rem = blockIdx.x, a = 0, len = NTS;
    while (rem >= len) { rem -= len; a++; len--; }
    const int b  = a + rem;
    const int i0 = a * TS, j0 = b * TS;

    const int tid = threadIdx.x;
    if (tid < HID) w2s[tid] = W2[tid];
    const float bb2 = 2.0f * b2[0];

    asm volatile("griddepcontrol.wait;" ::: "memory");

    // stage: i-side dup arrays (1024 float4) + j-side pair arrays (512 float4)
    for (int t = tid; t < 1536; t += 256) {
        if (t < 1024) {
            int h = t >> 3, q = t & 7;
            int c = (q & 3) * 4;                       // half2 column (4 per float4)
            float4 v = (q < 4)
                ? *(const float4*)&g_pid[h * Nn + i0 + c]
                : *(const float4*)&g_pjd[h * Nn + i0 + c];
            if (q < 4) *(float4*)&aeS[h][c] = v;
            else       *(float4*)&atS[h][c] = v;
        } else {
            int k = t - 1024;
            int h = k >> 2, q = k & 3;
            int c = (q & 1) * 4;
            float4 v = (q < 2)
                ? *(const float4*)&g_pjp[h * (Nn >> 1) + (j0 >> 1) + c]
                : *(const float4*)&g_pip[h * (Nn >> 1) + (j0 >> 1) + c];
            if (q < 2) *(float4*)&bjP[h][c] = v;
            else       *(float4*)&biP[h][c] = v;
        }
    }
    __syncthreads();

    const int g   = tid >> 7;        // h-group 0/1
    const int t2  = tid & 127;
    const int ii  = t2 >> 3;         // 0..15
    const int jj2 = t2 & 7;          // 0..7 -> j = 2*jj2, 2*jj2+1
    const int h0  = g * 64;

    float acc0 = 0.0f, acc1 = 0.0f;
#pragma unroll 8
    for (int hl = 0; hl < 64; hl++) {
        const int H = h0 + hl;
        __half2 ae = aeS[H][ii];
        __half2 at = atS[H][ii];
        __half2 bj = bjP[H][jj2];
        __half2 bi = biP[H][jj2];
        __half2 s  = __hadd2(tanh2(__hadd2(ae, bj)), tanh2(__hadd2(bi, at)));
        float w = w2s[H];
        acc0 = fmaf(w, __low2float(s),  acc0);
        acc1 = fmaf(w, __high2float(s), acc1);
    }

    // combine h-groups
    if (g == 0) {
        red[ii * TS + jj2 * 2 + 0] = acc0;
        red[ii * TS + jj2 * 2 + 1] = acc1;
    }
    __syncthreads();
    if (g == 1) {
        const float v0 = red[ii * TS + jj2 * 2 + 0] + acc0 + bb2;
        const float v1 = red[ii * TS + jj2 * 2 + 1] + acc1 + bb2;
        const int gi = i0 + ii;
        const int gj = j0 + jj2 * 2;
        *(float2*)&out[gi * Nn + gj] = make_float2(v0, v1);  // upper, coalesced
        out[(gj + 0) * Nn + gi] = v0;                        // mirror
        out[(gj + 1) * Nn + gi] = v1;
    }
}

extern "C" void kernel_launch(void* const* d_in, const int* in_sizes, int n_in,
                              void* d_out, int out_size) {
    const float* x  = (const float*)d_in[0];
    const float* W1 = (const float*)d_in[1];
    const float* b1 = (const float*)d_in[2];
    const float* W2 = (const float*)d_in[3];
    const float* b2 = (const float*)d_in[4];
    float* out = (float*)d_out;

    prep_kernel<<<dim3(32, 4), 256>>>(x, W1, b1);

    cudaLaunchConfig_t cfg = {};
    cfg.gridDim  = dim3(NUNITS);
    cfg.blockDim = dim3(256);
    cfg.dynamicSmemBytes = 0;
    cfg.stream = 0;
    cudaLaunchAttribute attr[1];
    attr[0].id = cudaLaunchAttributeProgrammaticStreamSerialization;
    attr[0].val.programmaticStreamSerializationAllowed = 1;
    cfg.attrs = attr;
    cfg.numAttrs = 1;
    cudaLaunchKernelEx(&cfg, pair_kernel, W2, b2, (float*)out);
}